// round 5
// baseline (speedup 1.0000x reference)
#include <cuda_runtime.h>
#include <cuda_bf16.h>

// SepConv: out[b,c,i,j] = sum_{u,v} img[b,c,i+u,j+v] * vert[b,u,i,j] * hori[b,v,i,j]
// Factorized: out = sum_u vert[u] * (sum_v hori[v] * img[i+u, j+v])
// R5: parity-split f32x2 packing with ONLY naturally-aligned operand pairs:
//   even taps -> (r0,r1),(r2,r3) FFMA2 on aligned data pairs + aligned weight pairs
//   odd taps  -> (r1,r2) FFMA2 on aligned data pair + hoisted packed weight pair,
//                r0/r3 scalar FFMA on register halves.
// Zero repacking movs in the hot loop; 41 issue slots per (u,c) vs 60 in R1.

#define KSZ 13
#define CC  3
#define WW  512
#define HH  512
#define WO  500
#define HO  500

#define TX  32                 // thread-groups in j; each thread covers 4 j
#define TY  8                  // output rows per block
#define JBLK (TX * 4)          // 128 output columns per block
#define TILE_ROWS (TY + KSZ - 1)   // 20 img rows
#define TILE_Q   36                // float4 per tile row (144 floats)

typedef unsigned long long ull;

__device__ __forceinline__ ull mul2(ull a, ull b) {
    ull d; asm("mul.rn.f32x2 %0, %1, %2;" : "=l"(d) : "l"(a), "l"(b)); return d;
}
__device__ __forceinline__ void fma2(ull& d, ull a, ull b) {
    asm("fma.rn.f32x2 %0, %1, %2, %0;" : "+l"(d) : "l"(a), "l"(b));
}
__device__ __forceinline__ ull pk(float a, float b) {
    ull r; asm("mov.b64 %0, {%1, %2};" : "=l"(r) : "f"(a), "f"(b)); return r;
}
__device__ __forceinline__ float2 unpk(ull a) {
    float2 r; asm("mov.b64 {%0, %1}, %2;" : "=f"(r.x), "=f"(r.y) : "l"(a)); return r;
}

__global__ __launch_bounds__(TX * TY, 2)
void sepconv_kernel(const float* __restrict__ img,
                    const float* __restrict__ hori,
                    const float* __restrict__ vert,
                    float* __restrict__ out) {
    __shared__ float4 s[CC][TILE_ROWS][TILE_Q];

    const int b  = blockIdx.z;
    const int j0 = blockIdx.x * JBLK;
    const int i0 = blockIdx.y * TY;
    const int tx = threadIdx.x, ty = threadIdx.y;
    const int tid = ty * TX + tx;

    // ---- cooperative load of the img tile (3 channels, 20 rows, 144 cols) ----
    const int NQ = CC * TILE_ROWS * TILE_Q;   // 2160 float4
    for (int f = tid; f < NQ; f += TX * TY) {
        int c   = f / (TILE_ROWS * TILE_Q);
        int rem = f - c * (TILE_ROWS * TILE_Q);
        int r   = rem / TILE_Q;
        int q   = rem - r * TILE_Q;
        int gx  = i0 + r; if (gx > WW - 1) gx = WW - 1;   // clamped rows feed only invalid outs
        int gy  = j0 + 4 * q;
        const float* base = img + (((size_t)b * CC + c) * WW + gx) * HH;
        float4 val;
        if (gy + 3 <= HH - 1) {
            val = *(const float4*)(base + gy);
        } else {
            int y0 = gy     < HH ? gy     : HH - 1;
            int y1 = gy + 1 < HH ? gy + 1 : HH - 1;
            int y2 = gy + 2 < HH ? gy + 2 : HH - 1;
            int y3 = gy + 3 < HH ? gy + 3 : HH - 1;
            val = make_float4(base[y0], base[y1], base[y2], base[y3]);
        }
        s[c][r][q] = val;
    }
    __syncthreads();

    const int i = i0 + ty;
    const int j = j0 + 4 * tx;
    if (i >= WO || j >= HO) return;   // HO%4==0 -> whole float4 valid when j<HO

    // ---- per-pixel horizontal weights (13 float4) + hoisted packed pairs ----
    float4 hw[KSZ];
    const float* hbase = hori + (((size_t)b * KSZ) * WO + i) * HO + j;
    #pragma unroll
    for (int v = 0; v < KSZ; v++)
        hw[v] = *(const float4*)(hbase + (size_t)v * WO * HO);

    // aligned weight pairs (free): ha[v]=(h.x,h.y), hb[v]=(h.z,h.w)
    // odd-middle weight pairs (12 movs total, hoisted): hm[m]=(h[2m+1].y, h[2m+1].z)
    ull hm[(KSZ - 1) / 2];
    #pragma unroll
    for (int m = 0; m < (KSZ - 1) / 2; m++)
        hm[m] = pk(hw[2 * m + 1].y, hw[2 * m + 1].z);

    // parity-split accumulators per channel
    ull accE01[CC], accE23[CC], accM12[CC];
    float accS0[CC], accS3[CC];
    #pragma unroll
    for (int c = 0; c < CC; c++) {
        accE01[c] = 0ull; accE23[c] = 0ull; accM12[c] = 0ull;
        accS0[c] = 0.f;   accS3[c] = 0.f;
    }

    const float* vbase = vert + (((size_t)b * KSZ) * WO + i) * HO + j;

    #pragma unroll
    for (int u = 0; u < KSZ; u++) {
        float4 vwf = *(const float4*)(vbase + (size_t)u * WO * HO);
        ull vw01 = pk(vwf.x, vwf.y);          // aligned halves -> free
        ull vw23 = pk(vwf.z, vwf.w);          // free
        ull vwM  = pk(vwf.y, vwf.z);          // 2 movs per u (hoisted out of c-loop)

        #pragma unroll
        for (int c = 0; c < CC; c++) {
            // 16-float window: cols j..j+15 of img row i+u
            const float4* rowp = &s[c][ty + u][0] + tx;
            float4 t0 = rowp[0], t1 = rowp[1], t2 = rowp[2], t3 = rowp[3];
            float w[16] = { t0.x, t0.y, t0.z, t0.w,  t1.x, t1.y, t1.z, t1.w,
                            t2.x, t2.y, t2.z, t2.w,  t3.x, t3.y, t3.z, t3.w };
            ull e[8];
            #pragma unroll
            for (int k = 0; k < 8; k++) e[k] = pk(w[2 * k], w[2 * k + 1]);  // aligned -> free

            // even taps v=0: init by mul
            ull tE01 = mul2(pk(hw[0].x, hw[0].y), e[0]);
            ull tE23 = mul2(pk(hw[0].z, hw[0].w), e[1]);
            // odd tap v=1: init by mul
            ull tM12 = mul2(hm[0], e[1]);
            float tS0 = hw[1].x * w[1];
            float tS3 = hw[1].w * w[4];

            #pragma unroll
            for (int v = 2; v < KSZ; v++) {
                if ((v & 1) == 0) {
                    fma2(tE01, pk(hw[v].x, hw[v].y), e[v / 2]);
                    fma2(tE23, pk(hw[v].z, hw[v].w), e[v / 2 + 1]);
                } else {
                    fma2(tM12, hm[(v - 1) / 2], e[(v + 1) / 2]);
                    tS0 = fmaf(hw[v].x, w[v], tS0);
                    tS3 = fmaf(hw[v].w, w[v + 3], tS3);
                }
            }

            // apply vert[u] to each parity piece (distributive over the final sum)
            fma2(accE01[c], vw01, tE01);
            fma2(accE23[c], vw23, tE23);
            fma2(accM12[c], vwM,  tM12);
            accS0[c] = fmaf(vwf.x, tS0, accS0[c]);
            accS3[c] = fmaf(vwf.w, tS3, accS3[c]);
        }
    }

    // ---- merge parity pieces and store ----
    #pragma unroll
    for (int c = 0; c < CC; c++) {
        float2 eE01 = unpk(accE01[c]);
        float2 eE23 = unpk(accE23[c]);
        float2 eM   = unpk(accM12[c]);
        float4 o;
        o.x = eE01.x + accS0[c];
        o.y = eE01.y + eM.x;
        o.z = eE23.x + eM.y;
        o.w = eE23.y + accS3[c];
        float* obase = out + (((size_t)b * CC + c) * WO + i) * HO + j;
        *(float4*)obase = o;
    }
}

extern "C" void kernel_launch(void* const* d_in, const int* in_sizes, int n_in,
                              void* d_out, int out_size) {
    const float* img  = (const float*)d_in[0];
    const float* hori = (const float*)d_in[1];
    const float* vert = (const float*)d_in[2];
    float* out = (float*)d_out;

    const int B = 8;
    dim3 block(TX, TY);                     // 256 threads
    dim3 grid((HO + JBLK - 1) / JBLK,       // 4
              (WO + TY - 1) / TY,           // 63
              B);                           // 8
    sepconv_kernel<<<grid, block>>>(img, hori, vert, out);
}

// round 6
// speedup vs baseline: 1.1923x; 1.1923x over previous
#include <cuda_runtime.h>
#include <cuda_bf16.h>

// SepConv: out[b,c,i,j] = sum_{u,v} img[b,c,i+u,j+v] * vert[b,u,i,j] * hori[b,v,i,j]
// Shapes: img[8,3,512,512], hori[8,13,500,500], vert[8,13,500,500], out[8,3,500,500]
// Factorized: out = sum_u vert[u] * (sum_v hori[v] * img[i+u, j+v])
// R6: R1 structure (best: 86.8us, ~74% of FFMA-rate ceiling). Changes aimed at
// fma-pipe occupancy, not FLOP count (which is minimal):
//   - TY=10, 320-thread blocks, launch_bounds(320,2) -> 20 warps/SM (was 16)
//   - vert[u+1] prefetch double-buffer (hide ~234+cyc L2 latency)
//   - row clamp removed (exact in i with TY=10)

#define KSZ 13
#define CC  3
#define WW  512
#define HH  512
#define WO  500
#define HO  500

#define TX  32                 // thread-groups in j; each thread covers 4 j
#define TY  10                 // output rows per block (500 = 50*10 exact)
#define JBLK (TX * 4)          // 128 output columns per block
#define TILE_ROWS (TY + KSZ - 1)   // 22 img rows
#define TILE_Q   36                // float4 per tile row (144 floats >= 128+15+1)

__global__ __launch_bounds__(TX * TY, 2)
void sepconv_kernel(const float* __restrict__ img,
                    const float* __restrict__ hori,
                    const float* __restrict__ vert,
                    float* __restrict__ out) {
    __shared__ float4 s[CC][TILE_ROWS][TILE_Q];

    const int b  = blockIdx.z;
    const int j0 = blockIdx.x * JBLK;
    const int i0 = blockIdx.y * TY;
    const int tx = threadIdx.x, ty = threadIdx.y;
    const int tid = ty * TX + tx;

    // ---- cooperative load of the img tile (3 channels, 22 rows, 144 cols) ----
    const int NQ = CC * TILE_ROWS * TILE_Q;   // 2376 float4
    for (int f = tid; f < NQ; f += TX * TY) {
        int c   = f / (TILE_ROWS * TILE_Q);
        int rem = f - c * (TILE_ROWS * TILE_Q);
        int r   = rem / TILE_Q;
        int q   = rem - r * TILE_Q;
        int gx  = i0 + r;                      // i0 <= 490, r <= 21 -> gx <= 511 exact
        int gy  = j0 + 4 * q;
        const float* base = img + (((size_t)b * CC + c) * WW + gx) * HH;
        float4 val;
        if (gy + 3 <= HH - 1) {
            val = *(const float4*)(base + gy);
        } else {
            int y0 = gy     < HH ? gy     : HH - 1;
            int y1 = gy + 1 < HH ? gy + 1 : HH - 1;
            int y2 = gy + 2 < HH ? gy + 2 : HH - 1;
            int y3 = gy + 3 < HH ? gy + 3 : HH - 1;
            val = make_float4(base[y0], base[y1], base[y2], base[y3]);
        }
        s[c][r][q] = val;
    }
    __syncthreads();

    const int i = i0 + ty;            // always < 500 (50*10 exact)
    const int j = j0 + 4 * tx;
    if (j >= HO) return;              // HO%4==0 -> whole float4 valid when j<HO

    // ---- per-pixel horizontal weights, kept in registers (13 x float4) ----
    float4 hw[KSZ];
    const float* hbase = hori + (((size_t)b * KSZ) * WO + i) * HO + j;
    #pragma unroll
    for (int v = 0; v < KSZ; v++)
        hw[v] = *(const float4*)(hbase + (size_t)v * WO * HO);

    float4 acc[CC];
    #pragma unroll
    for (int c = 0; c < CC; c++) acc[c] = make_float4(0.f, 0.f, 0.f, 0.f);

    const float* vbase = vert + (((size_t)b * KSZ) * WO + i) * HO + j;

    // software-pipelined vert loads: vw for iteration u is fetched at u-1
    float4 vw_next = *(const float4*)(vbase);

    #pragma unroll
    for (int u = 0; u < KSZ; u++) {
        float4 vw = vw_next;
        if (u + 1 < KSZ)
            vw_next = *(const float4*)(vbase + (size_t)(u + 1) * WO * HO);

        #pragma unroll
        for (int c = 0; c < CC; c++) {
            // 16-float register window covering columns j .. j+15 of img row i+u
            const float4* row4 = &s[c][ty + u][0] + tx;
            float w[16];
            #pragma unroll
            for (int k = 0; k < 4; k++) {
                float4 t4 = row4[k];
                w[4*k+0] = t4.x; w[4*k+1] = t4.y; w[4*k+2] = t4.z; w[4*k+3] = t4.w;
            }
            float r0 = 0.f, r1 = 0.f, r2 = 0.f, r3 = 0.f;
            #pragma unroll
            for (int v = 0; v < KSZ; v++) {
                r0 = fmaf(hw[v].x, w[v + 0], r0);
                r1 = fmaf(hw[v].y, w[v + 1], r1);
                r2 = fmaf(hw[v].z, w[v + 2], r2);
                r3 = fmaf(hw[v].w, w[v + 3], r3);
            }
            acc[c].x = fmaf(vw.x, r0, acc[c].x);
            acc[c].y = fmaf(vw.y, r1, acc[c].y);
            acc[c].z = fmaf(vw.z, r2, acc[c].z);
            acc[c].w = fmaf(vw.w, r3, acc[c].w);
        }
    }

    #pragma unroll
    for (int c = 0; c < CC; c++) {
        float* obase = out + (((size_t)b * CC + c) * WO + i) * HO + j;
        *(float4*)obase = acc[c];
    }
}

extern "C" void kernel_launch(void* const* d_in, const int* in_sizes, int n_in,
                              void* d_out, int out_size) {
    const float* img  = (const float*)d_in[0];
    const float* hori = (const float*)d_in[1];
    const float* vert = (const float*)d_in[2];
    float* out = (float*)d_out;

    const int B = 8;
    dim3 block(TX, TY);                     // 320 threads
    dim3 grid((HO + JBLK - 1) / JBLK,       // 4
              WO / TY,                      // 50 (exact)
              B);                           // 8
    sepconv_kernel<<<grid, block>>>(img, hori, vert, out);
}